// round 4
// baseline (speedup 1.0000x reference)
#include <cuda_runtime.h>

#define NN 50000
#define NE 800000
#define EP (NE + NN)        // edges + self loops
#define C  64
#define H  4
#define HC 256              // H * C
#define NEG_SLOPE 0.2f
#define BN_EPS 1e-5f

// ---------------- scratch (static device globals; no runtime alloc) ----------
__device__ float4 g_xh4[NN * (HC / 4)];   // xh: [NN][64] float4  (51.2 MB, fits L2)
__device__ float4 g_alsrc4[NN];           // per-node src logits, 4 heads
__device__ float4 g_aldst4[NN];           // per-node dst logits, 4 heads
__device__ float4 g_p4[EP];               // per-edge softmax numerators, 4 heads
__device__ float  g_x1[NN * C];           // layer-1 post BN/ReLU
__device__ float  g_tmp[NN * C];          // GAT output scratch
__device__ int    g_cnt[NN];
__device__ int    g_cur[NN];
__device__ int    g_off[NN + 1];
__device__ int    g_csr[EP];
__device__ float  g_bn[4 * C];            // [sum | sumsq | scale | shift]
__device__ int    g_is32;                 // 1 -> edge_index is int32, 0 -> int64

__device__ __forceinline__ float lrelu(float v) { return v > 0.f ? v : NEG_SLOPE * v; }

// Safe edge-index read: dtype chosen at runtime, result clamped into [0, NN).
__device__ __forceinline__ int edge_val(const void* ei, int pos) {
    long long v = g_is32 ? (long long)((const int*)ei)[pos]
                         : ((const long long*)ei)[pos];
    int r = (int)v;
    if (r < 0) r = 0;
    if (r >= NN) r = NN - 1;
    return r;
}

// ---------------- dtype detection -------------------------------------------
// int64 little-endian values < 2^31  =>  every odd 32-bit word is 0.
__global__ void k_detect(const int* __restrict__ ei32) {
    __shared__ int s_any;
    if (threadIdx.x == 0) s_any = 0;
    __syncthreads();
    for (int k = threadIdx.x; k < 4096; k += 256) {
        if (ei32[2 * k + 1] != 0) s_any = 1;   // benign race
    }
    __syncthreads();
    if (threadIdx.x == 0) g_is32 = s_any;
}

// ---------------- CSR build --------------------------------------------------
__global__ void k_zero_cnt() {
    int i = blockIdx.x * blockDim.x + threadIdx.x;
    if (i < NN) { g_cnt[i] = 0; g_cur[i] = 0; }
}

__global__ void k_count(const void* __restrict__ ei) {
    int e = blockIdx.x * blockDim.x + threadIdx.x;
    if (e >= EP) return;
    int dst = (e < NE) ? edge_val(ei, NE + e) : (e - NE);
    atomicAdd(&g_cnt[dst], 1);
}

__global__ void k_scan() {  // single-block exclusive scan of g_cnt -> g_off
    __shared__ int sdata[1024];
    __shared__ int s_run;
    int t = threadIdx.x;
    if (t == 0) s_run = 0;
    __syncthreads();
    for (int base = 0; base < NN; base += 1024) {
        int v = (base + t < NN) ? g_cnt[base + t] : 0;
        sdata[t] = v;
        __syncthreads();
        for (int off = 1; off < 1024; off <<= 1) {
            int add = 0;
            if (t >= off) add = sdata[t - off];
            __syncthreads();
            if (t >= off) sdata[t] += add;
            __syncthreads();
        }
        if (base + t < NN) g_off[base + t] = s_run + sdata[t] - v;
        __syncthreads();
        if (t == 0) s_run += sdata[1023];
        __syncthreads();
    }
    if (t == 0) g_off[NN] = s_run;
}

__global__ void k_fill(const void* __restrict__ ei) {
    int e = blockIdx.x * blockDim.x + threadIdx.x;
    if (e >= EP) return;
    int src, dst;
    if (e < NE) { src = edge_val(ei, e); dst = edge_val(ei, NE + e); }
    else        { src = e - NE;          dst = e - NE; }
    int idx = g_off[dst] + atomicAdd(&g_cur[dst], 1);
    if (idx >= 0 && idx < EP) g_csr[idx] = src;
}

// ---------------- GEMM: xh[n, j] = sum_k xin[n,k] * W[k,j] -------------------
// xin_ext == nullptr -> read from g_x1
__global__ void k_gemm(const float* __restrict__ xin_ext, const float* __restrict__ W) {
    const float* xin = xin_ext ? xin_ext : g_x1;
    float* xh = (float*)g_xh4;              // scalar view (downcast is safe)
    __shared__ float xs[16 * 64];
    int t = threadIdx.x;
    int row0 = blockIdx.x * 16;
#pragma unroll
    for (int i = 0; i < 4; i++) {
        int l = t + i * 256;
        xs[l] = xin[row0 * 64 + l];         // NN % 16 == 0, never OOB
    }
    __syncthreads();
    float acc[16];
#pragma unroll
    for (int r = 0; r < 16; r++) acc[r] = 0.f;
    for (int k = 0; k < 64; k++) {
        float w = __ldg(&W[k * HC + t]);
#pragma unroll
        for (int r = 0; r < 16; r++) acc[r] = fmaf(xs[r * 64 + k], w, acc[r]);
    }
#pragma unroll
    for (int r = 0; r < 16; r++) {
        xh[(size_t)(row0 + r) * HC + t] = acc[r];
    }
}

// ---------------- attention logits al_src / al_dst ---------------------------
__global__ void k_al(const float* __restrict__ asrc, const float* __restrict__ adst) {
    __shared__ float ss[256], sd[256];
    const float* xh = (const float*)g_xh4;
    int n = blockIdx.x;
    int t = threadIdx.x;
    float v = xh[(size_t)n * HC + t];
    ss[t] = v * __ldg(&asrc[t]);
    sd[t] = v * __ldg(&adst[t]);
    __syncthreads();
#pragma unroll
    for (int off = 32; off >= 1; off >>= 1) {
        if ((t & 63) < off) { ss[t] += ss[t + off]; sd[t] += sd[t + off]; }
        __syncthreads();
    }
    if ((t & 63) == 0) {
        int h = t >> 6;
        ((float*)&g_alsrc4[n])[h] = ss[t];
        ((float*)&g_aldst4[n])[h] = sd[t];
    }
}

// ---------------- fused softmax + aggregate (one warp per node) --------------
// out_ext == nullptr -> write to g_tmp
__global__ void k_agg(const float* __restrict__ bias, float* __restrict__ out_ext) {
    float* out = out_ext ? out_ext : g_tmp;
    __shared__ float4 sm4[8][64];           // one 256-float row per warp
    int warp = threadIdx.x >> 5, lane = threadIdx.x & 31;
    int n = blockIdx.x * 8 + warp;
    if (n >= NN) return;
    int beg = g_off[n], end = g_off[n + 1];
    float4 ad = g_aldst4[n];

    // pass A: segment max per head
    float m0 = -1e30f, m1 = -1e30f, m2 = -1e30f, m3 = -1e30f;
    for (int i = beg + lane; i < end; i += 32) {
        int s = g_csr[i];
        float4 as = g_alsrc4[s];
        m0 = fmaxf(m0, lrelu(as.x + ad.x));
        m1 = fmaxf(m1, lrelu(as.y + ad.y));
        m2 = fmaxf(m2, lrelu(as.z + ad.z));
        m3 = fmaxf(m3, lrelu(as.w + ad.w));
    }
#pragma unroll
    for (int o = 16; o; o >>= 1) {
        m0 = fmaxf(m0, __shfl_xor_sync(0xffffffffu, m0, o));
        m1 = fmaxf(m1, __shfl_xor_sync(0xffffffffu, m1, o));
        m2 = fmaxf(m2, __shfl_xor_sync(0xffffffffu, m2, o));
        m3 = fmaxf(m3, __shfl_xor_sync(0xffffffffu, m3, o));
    }

    // pass B: p = exp(e - m), denom
    float d0 = 0.f, d1 = 0.f, d2 = 0.f, d3 = 0.f;
    for (int i = beg + lane; i < end; i += 32) {
        int s = g_csr[i];
        float4 as = g_alsrc4[s];
        float p0 = __expf(lrelu(as.x + ad.x) - m0);
        float p1 = __expf(lrelu(as.y + ad.y) - m1);
        float p2 = __expf(lrelu(as.z + ad.z) - m2);
        float p3 = __expf(lrelu(as.w + ad.w) - m3);
        d0 += p0; d1 += p1; d2 += p2; d3 += p3;
        g_p4[i] = make_float4(p0, p1, p2, p3);
    }
#pragma unroll
    for (int o = 16; o; o >>= 1) {
        d0 += __shfl_xor_sync(0xffffffffu, d0, o);
        d1 += __shfl_xor_sync(0xffffffffu, d1, o);
        d2 += __shfl_xor_sync(0xffffffffu, d2, o);
        d3 += __shfl_xor_sync(0xffffffffu, d3, o);
    }
    float iv0 = 1.f / (d0 + 1e-16f), iv1 = 1.f / (d1 + 1e-16f);
    float iv2 = 1.f / (d2 + 1e-16f), iv3 = 1.f / (d3 + 1e-16f);

    // pass C: gather xh[src] and accumulate alpha-weighted sum (whole warp per edge)
    int hsel = lane >> 4;                       // 0 or 1
    float iva = hsel ? iv1 : iv0;               // head for acc0 (heads 0/1)
    float ivb = hsel ? iv3 : iv2;               // head for acc1 (heads 2/3)
    float4 acc0 = make_float4(0.f, 0.f, 0.f, 0.f);
    float4 acc1 = make_float4(0.f, 0.f, 0.f, 0.f);
    for (int i = beg; i < end; i++) {
        int s = g_csr[i];
        float4 p4 = g_p4[i];
        float a0 = (hsel ? p4.y : p4.x) * iva;
        float a1 = (hsel ? p4.w : p4.z) * ivb;
        const float4* xr = &g_xh4[(size_t)s * (HC / 4)];
        float4 v0 = xr[lane];
        float4 v1 = xr[32 + lane];
        acc0.x = fmaf(a0, v0.x, acc0.x); acc0.y = fmaf(a0, v0.y, acc0.y);
        acc0.z = fmaf(a0, v0.z, acc0.z); acc0.w = fmaf(a0, v0.w, acc0.w);
        acc1.x = fmaf(a1, v1.x, acc1.x); acc1.y = fmaf(a1, v1.y, acc1.y);
        acc1.z = fmaf(a1, v1.z, acc1.z); acc1.w = fmaf(a1, v1.w, acc1.w);
    }
    sm4[warp][lane]      = acc0;
    sm4[warp][32 + lane] = acc1;
    __syncwarp();
    const float* smf = (const float*)sm4[warp];
#pragma unroll
    for (int j = 0; j < 2; j++) {
        int c = lane + 32 * j;
        float v = (smf[c] + smf[c + 64] + smf[c + 128] + smf[c + 192]) * 0.25f
                  + __ldg(&bias[c]);
        out[(size_t)n * C + c] = v;
    }
}

// ---------------- BatchNorm --------------------------------------------------
__global__ void k_bn_zero() {
    int t = threadIdx.x;
    if (t < 128) g_bn[t] = 0.f;
}

// xin_ext == nullptr -> read g_tmp
__global__ void k_bn_sum(const float* __restrict__ xin_ext) {
    const float* x = xin_ext ? xin_ext : g_tmp;
    __shared__ float s1[256], s2[256];
    int t = threadIdx.x;
    int c = t & 63, q = t >> 6;
    int r0 = blockIdx.x * 200;
    float s = 0.f, ss = 0.f;
    for (int r = r0 + q; r < r0 + 200; r += 4) {
        float v = x[(size_t)r * 64 + c];
        s += v; ss += v * v;
    }
    s1[t] = s; s2[t] = ss;
    __syncthreads();
    if (t < 128) { s1[t] += s1[t + 128]; s2[t] += s2[t + 128]; }
    __syncthreads();
    if (t < 64) {
        atomicAdd(&g_bn[c],      s1[t] + s1[t + 64]);
        atomicAdd(&g_bn[64 + c], s2[t] + s2[t + 64]);
    }
}

__global__ void k_bn_final(const float* __restrict__ gamma, const float* __restrict__ beta) {
    int c = threadIdx.x;
    if (c >= 64) return;
    float mean = g_bn[c] * (1.f / NN);
    float var  = g_bn[64 + c] * (1.f / NN) - mean * mean;
    float sc = __ldg(&gamma[c]) * rsqrtf(var + BN_EPS);
    g_bn[128 + c] = sc;
    g_bn[192 + c] = __ldg(&beta[c]) - mean * sc;
}

// in_ext == nullptr -> read g_tmp ; out_ext == nullptr -> write g_x1
__global__ void k_bn_apply(const float* __restrict__ in_ext, float* __restrict__ out_ext) {
    const float* in = in_ext ? in_ext : g_tmp;
    float* out = out_ext ? out_ext : g_x1;
    int i = blockIdx.x * blockDim.x + threadIdx.x;
    if (i >= NN * C) return;
    int c = i & 63;
    float v = g_bn[128 + c] * in[i] + g_bn[192 + c];
    out[i] = fmaxf(v, 0.f);
}

// ---------------- launch -----------------------------------------------------
extern "C" void kernel_launch(void* const* d_in, const int* in_sizes, int n_in,
                              void* d_out, int out_size) {
    const float* x  = (const float*)d_in[0];
    const void*  ei = d_in[1];                 // int32 or int64, detected on device
    float* out = (float*)d_out;

    const float* W[2]     = {(const float*)d_in[3],  (const float*)d_in[9]};
    const float* asrc[2]  = {(const float*)d_in[4],  (const float*)d_in[10]};
    const float* adst[2]  = {(const float*)d_in[5],  (const float*)d_in[11]};
    const float* bias[2]  = {(const float*)d_in[6],  (const float*)d_in[12]};
    const float* gamma[2] = {(const float*)d_in[7],  (const float*)d_in[13]};
    const float* beta[2]  = {(const float*)d_in[8],  (const float*)d_in[14]};

    // dtype detection + CSR build (shared by both layers)
    k_detect<<<1, 256>>>((const int*)ei);
    k_zero_cnt<<<(NN + 255) / 256, 256>>>();
    k_count<<<(EP + 255) / 256, 256>>>(ei);
    k_scan<<<1, 1024>>>();
    k_fill<<<(EP + 255) / 256, 256>>>(ei);

    bool both_outputs = (out_size >= 2 * NN * C);
    float* saved_ptr = both_outputs ? (out + (size_t)NN * C) : nullptr; // nullptr -> g_tmp

    // ---- layer 0: x -> (GAT) g_tmp -> (BN/ReLU) g_x1
    k_gemm<<<NN / 16, 256>>>(x, W[0]);
    k_al<<<NN, 256>>>(asrc[0], adst[0]);
    k_agg<<<(NN + 7) / 8, 256>>>(bias[0], nullptr);              // -> g_tmp
    k_bn_zero<<<1, 128>>>();
    k_bn_sum<<<250, 256>>>(nullptr);                              // from g_tmp
    k_bn_final<<<1, 64>>>(gamma[0], beta[0]);
    k_bn_apply<<<(NN * C + 255) / 256, 256>>>(nullptr, nullptr);  // g_tmp -> g_x1

    // ---- layer 1: g_x1 -> (GAT) saved -> (BN/ReLU) out
    k_gemm<<<NN / 16, 256>>>(nullptr, W[1]);                      // from g_x1
    k_al<<<NN, 256>>>(asrc[1], adst[1]);
    k_agg<<<(NN + 7) / 8, 256>>>(bias[1], saved_ptr);             // -> out[NN*C:] (saved)
    k_bn_zero<<<1, 128>>>();
    k_bn_sum<<<250, 256>>>(saved_ptr);                            // from saved
    k_bn_final<<<1, 64>>>(gamma[1], beta[1]);
    k_bn_apply<<<(NN * C + 255) / 256, 256>>>(saved_ptr, out);    // saved -> out[:NN*C]
}

// round 5
// speedup vs baseline: 1.7504x; 1.7504x over previous
#include <cuda_runtime.h>

#define NN 50000
#define NE 800000
#define EP (NE + NN)        // edges + self loops
#define C  64
#define H  4
#define HC 256              // H * C
#define NEG_SLOPE 0.2f
#define BN_EPS 1e-5f

#define SCAN_BLK 1024
#define NSCAN ((NN + SCAN_BLK - 1) / SCAN_BLK)   // 49

// ---------------- scratch (static device globals; no runtime alloc) ----------
__device__ float4 g_xh4[NN * (HC / 4)];   // xh: [NN][64] float4  (51.2 MB, fits L2)
__device__ float4 g_alsrc4[NN];           // per-node src logits, 4 heads
__device__ float4 g_aldst4[NN];           // per-node dst logits, 4 heads
__device__ float4 g_p4[EP];               // per-edge softmax numerators, 4 heads
__device__ float  g_x1[NN * C];           // layer-1 post BN/ReLU
__device__ float  g_tmp[NN * C];          // GAT output scratch
__device__ int    g_cnt[NN];
__device__ int    g_cur[NN];
__device__ int    g_off[NN + 1];
__device__ int    g_csr[EP];
__device__ int    g_bsum[NSCAN];
__device__ int    g_boff[NSCAN + 1];
__device__ float  g_bn[4 * C];            // [sum | sumsq | scale | shift]
__device__ int    g_is32;                 // 1 -> edge_index is int32, 0 -> int64

__device__ __forceinline__ float lrelu(float v) { return v > 0.f ? v : NEG_SLOPE * v; }

// Safe edge-index read: dtype chosen at runtime, result clamped into [0, NN).
__device__ __forceinline__ int edge_val(const void* ei, int pos) {
    long long v = g_is32 ? (long long)((const int*)ei)[pos]
                         : ((const long long*)ei)[pos];
    int r = (int)v;
    if (r < 0) r = 0;
    if (r >= NN) r = NN - 1;
    return r;
}

// ---------------- dtype detection -------------------------------------------
// int64 little-endian values < 2^31  =>  every odd 32-bit word is 0.
__global__ void k_detect(const int* __restrict__ ei32) {
    __shared__ int s_any;
    if (threadIdx.x == 0) s_any = 0;
    __syncthreads();
    for (int k = threadIdx.x; k < 4096; k += 256) {
        if (ei32[2 * k + 1] != 0) s_any = 1;   // benign race
    }
    __syncthreads();
    if (threadIdx.x == 0) g_is32 = s_any;
}

// ---------------- CSR build --------------------------------------------------
__global__ void k_zero_cnt() {
    int i = blockIdx.x * blockDim.x + threadIdx.x;
    if (i < NN) { g_cnt[i] = 0; g_cur[i] = 0; }
}

__global__ void k_count(const void* __restrict__ ei) {
    int e = blockIdx.x * blockDim.x + threadIdx.x;
    if (e >= EP) return;
    int dst = (e < NE) ? edge_val(ei, NE + e) : (e - NE);
    atomicAdd(&g_cnt[dst], 1);
}

// ---- decoupled 3-phase scan of g_cnt -> g_off -------------------------------
__global__ void k_blocksum() {   // 49 blocks x 256 threads
    __shared__ int sd[256];
    int t = threadIdx.x;
    int base = blockIdx.x * SCAN_BLK;
    int s = 0;
#pragma unroll
    for (int j = 0; j < 4; j++) {
        int i = base + t + j * 256;
        s += (i < NN) ? g_cnt[i] : 0;
    }
    sd[t] = s;
    __syncthreads();
    for (int o = 128; o >= 1; o >>= 1) {
        if (t < o) sd[t] += sd[t + o];
        __syncthreads();
    }
    if (t == 0) g_bsum[blockIdx.x] = sd[0];
}

__global__ void k_scanblk() {    // 1 block, thread 0 serial over 49 entries
    if (threadIdx.x == 0) {
        int run = 0;
        for (int b = 0; b < NSCAN; b++) { g_boff[b] = run; run += g_bsum[b]; }
        g_boff[NSCAN] = run;
        g_off[NN] = run;
    }
}

__global__ void k_localscan() {  // 49 blocks x 1024: warp-shuffle exclusive scan
    __shared__ int swarp[32];
    int t = threadIdx.x, lane = t & 31, wid = t >> 5;
    int i = blockIdx.x * SCAN_BLK + t;
    int v = (i < NN) ? g_cnt[i] : 0;
    int incl = v;
#pragma unroll
    for (int o = 1; o < 32; o <<= 1) {
        int u = __shfl_up_sync(0xffffffffu, incl, o);
        if (lane >= o) incl += u;
    }
    if (lane == 31) swarp[wid] = incl;
    __syncthreads();
    if (wid == 0) {
        int s = swarp[lane];
        int in2 = s;
#pragma unroll
        for (int o = 1; o < 32; o <<= 1) {
            int u = __shfl_up_sync(0xffffffffu, in2, o);
            if (lane >= o) in2 += u;
        }
        swarp[lane] = in2 - s;   // exclusive warp base
    }
    __syncthreads();
    if (i < NN) g_off[i] = (incl - v) + swarp[wid] + g_boff[blockIdx.x];
}

__global__ void k_fill(const void* __restrict__ ei) {
    int e = blockIdx.x * blockDim.x + threadIdx.x;
    if (e >= EP) return;
    int src, dst;
    if (e < NE) { src = edge_val(ei, e); dst = edge_val(ei, NE + e); }
    else        { src = e - NE;          dst = e - NE; }
    int idx = g_off[dst] + atomicAdd(&g_cur[dst], 1);
    if (idx >= 0 && idx < EP) g_csr[idx] = src;
}

// ---------------- GEMM: xh[n, j] = sum_k xin[n,k] * W[k,j] -------------------
// xin_ext == nullptr -> read from g_x1
__global__ void k_gemm(const float* __restrict__ xin_ext, const float* __restrict__ W) {
    const float* xin = xin_ext ? xin_ext : g_x1;
    float* xh = (float*)g_xh4;              // scalar view (downcast is safe)
    __shared__ float xs[16 * 64];
    int t = threadIdx.x;
    int row0 = blockIdx.x * 16;
#pragma unroll
    for (int i = 0; i < 4; i++) {
        int l = t + i * 256;
        xs[l] = xin[row0 * 64 + l];         // NN % 16 == 0, never OOB
    }
    __syncthreads();
    float acc[16];
#pragma unroll
    for (int r = 0; r < 16; r++) acc[r] = 0.f;
    for (int k = 0; k < 64; k++) {
        float w = __ldg(&W[k * HC + t]);
#pragma unroll
        for (int r = 0; r < 16; r++) acc[r] = fmaf(xs[r * 64 + k], w, acc[r]);
    }
#pragma unroll
    for (int r = 0; r < 16; r++) {
        xh[(size_t)(row0 + r) * HC + t] = acc[r];
    }
}

// ---------------- attention logits al_src / al_dst ---------------------------
__global__ void k_al(const float* __restrict__ asrc, const float* __restrict__ adst) {
    __shared__ float ss[256], sd[256];
    const float* xh = (const float*)g_xh4;
    int n = blockIdx.x;
    int t = threadIdx.x;
    float v = xh[(size_t)n * HC + t];
    ss[t] = v * __ldg(&asrc[t]);
    sd[t] = v * __ldg(&adst[t]);
    __syncthreads();
#pragma unroll
    for (int off = 32; off >= 1; off >>= 1) {
        if ((t & 63) < off) { ss[t] += ss[t + off]; sd[t] += sd[t + off]; }
        __syncthreads();
    }
    if ((t & 63) == 0) {
        int h = t >> 6;
        ((float*)&g_alsrc4[n])[h] = ss[t];
        ((float*)&g_aldst4[n])[h] = sd[t];
    }
}

// ---------------- fused softmax + aggregate (one warp per node) --------------
// out_ext == nullptr -> write to g_tmp
__global__ void k_agg(const float* __restrict__ bias, float* __restrict__ out_ext) {
    float* out = out_ext ? out_ext : g_tmp;
    __shared__ float4 sm4[8][64];           // one 256-float row per warp
    int warp = threadIdx.x >> 5, lane = threadIdx.x & 31;
    int n = blockIdx.x * 8 + warp;
    if (n >= NN) return;
    int beg = g_off[n], end = g_off[n + 1];
    float4 ad = g_aldst4[n];

    // pass A: segment max per head
    float m0 = -1e30f, m1 = -1e30f, m2 = -1e30f, m3 = -1e30f;
    for (int i = beg + lane; i < end; i += 32) {
        int s = g_csr[i];
        float4 as = g_alsrc4[s];
        m0 = fmaxf(m0, lrelu(as.x + ad.x));
        m1 = fmaxf(m1, lrelu(as.y + ad.y));
        m2 = fmaxf(m2, lrelu(as.z + ad.z));
        m3 = fmaxf(m3, lrelu(as.w + ad.w));
    }
#pragma unroll
    for (int o = 16; o; o >>= 1) {
        m0 = fmaxf(m0, __shfl_xor_sync(0xffffffffu, m0, o));
        m1 = fmaxf(m1, __shfl_xor_sync(0xffffffffu, m1, o));
        m2 = fmaxf(m2, __shfl_xor_sync(0xffffffffu, m2, o));
        m3 = fmaxf(m3, __shfl_xor_sync(0xffffffffu, m3, o));
    }

    // pass B: p = exp(e - m), denom
    float d0 = 0.f, d1 = 0.f, d2 = 0.f, d3 = 0.f;
    for (int i = beg + lane; i < end; i += 32) {
        int s = g_csr[i];
        float4 as = g_alsrc4[s];
        float p0 = __expf(lrelu(as.x + ad.x) - m0);
        float p1 = __expf(lrelu(as.y + ad.y) - m1);
        float p2 = __expf(lrelu(as.z + ad.z) - m2);
        float p3 = __expf(lrelu(as.w + ad.w) - m3);
        d0 += p0; d1 += p1; d2 += p2; d3 += p3;
        g_p4[i] = make_float4(p0, p1, p2, p3);
    }
#pragma unroll
    for (int o = 16; o; o >>= 1) {
        d0 += __shfl_xor_sync(0xffffffffu, d0, o);
        d1 += __shfl_xor_sync(0xffffffffu, d1, o);
        d2 += __shfl_xor_sync(0xffffffffu, d2, o);
        d3 += __shfl_xor_sync(0xffffffffu, d3, o);
    }
    float iv0 = 1.f / (d0 + 1e-16f), iv1 = 1.f / (d1 + 1e-16f);
    float iv2 = 1.f / (d2 + 1e-16f), iv3 = 1.f / (d3 + 1e-16f);

    // pass C: gather xh[src] and accumulate alpha-weighted sum (whole warp per edge)
    int hsel = lane >> 4;                       // 0 or 1
    float iva = hsel ? iv1 : iv0;               // head for acc0 (heads 0/1)
    float ivb = hsel ? iv3 : iv2;               // head for acc1 (heads 2/3)
    float4 acc0 = make_float4(0.f, 0.f, 0.f, 0.f);
    float4 acc1 = make_float4(0.f, 0.f, 0.f, 0.f);
    for (int i = beg; i < end; i++) {
        int s = g_csr[i];
        float4 p4 = g_p4[i];
        float a0 = (hsel ? p4.y : p4.x) * iva;
        float a1 = (hsel ? p4.w : p4.z) * ivb;
        const float4* xr = &g_xh4[(size_t)s * (HC / 4)];
        float4 v0 = xr[lane];
        float4 v1 = xr[32 + lane];
        acc0.x = fmaf(a0, v0.x, acc0.x); acc0.y = fmaf(a0, v0.y, acc0.y);
        acc0.z = fmaf(a0, v0.z, acc0.z); acc0.w = fmaf(a0, v0.w, acc0.w);
        acc1.x = fmaf(a1, v1.x, acc1.x); acc1.y = fmaf(a1, v1.y, acc1.y);
        acc1.z = fmaf(a1, v1.z, acc1.z); acc1.w = fmaf(a1, v1.w, acc1.w);
    }
    sm4[warp][lane]      = acc0;
    sm4[warp][32 + lane] = acc1;
    __syncwarp();
    const float* smf = (const float*)sm4[warp];
#pragma unroll
    for (int j = 0; j < 2; j++) {
        int c = lane + 32 * j;
        float v = (smf[c] + smf[c + 64] + smf[c + 128] + smf[c + 192]) * 0.25f
                  + __ldg(&bias[c]);
        out[(size_t)n * C + c] = v;
    }
}

// ---------------- BatchNorm --------------------------------------------------
__global__ void k_bn_zero() {
    int t = threadIdx.x;
    if (t < 128) g_bn[t] = 0.f;
}

// xin_ext == nullptr -> read g_tmp
__global__ void k_bn_sum(const float* __restrict__ xin_ext) {
    const float* x = xin_ext ? xin_ext : g_tmp;
    __shared__ float s1[256], s2[256];
    int t = threadIdx.x;
    int c = t & 63, q = t >> 6;
    int r0 = blockIdx.x * 200;
    float s = 0.f, ss = 0.f;
    for (int r = r0 + q; r < r0 + 200; r += 4) {
        float v = x[(size_t)r * 64 + c];
        s += v; ss += v * v;
    }
    s1[t] = s; s2[t] = ss;
    __syncthreads();
    if (t < 128) { s1[t] += s1[t + 128]; s2[t] += s2[t + 128]; }
    __syncthreads();
    if (t < 64) {
        atomicAdd(&g_bn[c],      s1[t] + s1[t + 64]);
        atomicAdd(&g_bn[64 + c], s2[t] + s2[t + 64]);
    }
}

__global__ void k_bn_final(const float* __restrict__ gamma, const float* __restrict__ beta) {
    int c = threadIdx.x;
    if (c >= 64) return;
    float mean = g_bn[c] * (1.f / NN);
    float var  = g_bn[64 + c] * (1.f / NN) - mean * mean;
    float sc = __ldg(&gamma[c]) * rsqrtf(var + BN_EPS);
    g_bn[128 + c] = sc;
    g_bn[192 + c] = __ldg(&beta[c]) - mean * sc;
}

// in_ext == nullptr -> read g_tmp ; out_ext == nullptr -> write g_x1
__global__ void k_bn_apply(const float* __restrict__ in_ext, float* __restrict__ out_ext) {
    const float* in = in_ext ? in_ext : g_tmp;
    float* out = out_ext ? out_ext : g_x1;
    int i = blockIdx.x * blockDim.x + threadIdx.x;
    if (i >= NN * C) return;
    int c = i & 63;
    float v = g_bn[128 + c] * in[i] + g_bn[192 + c];
    out[i] = fmaxf(v, 0.f);
}

// ---------------- launch -----------------------------------------------------
extern "C" void kernel_launch(void* const* d_in, const int* in_sizes, int n_in,
                              void* d_out, int out_size) {
    const float* x  = (const float*)d_in[0];
    const void*  ei = d_in[1];                 // int32 or int64, detected on device
    float* out = (float*)d_out;

    const float* W[2]     = {(const float*)d_in[3],  (const float*)d_in[9]};
    const float* asrc[2]  = {(const float*)d_in[4],  (const float*)d_in[10]};
    const float* adst[2]  = {(const float*)d_in[5],  (const float*)d_in[11]};
    const float* bias[2]  = {(const float*)d_in[6],  (const float*)d_in[12]};
    const float* gamma[2] = {(const float*)d_in[7],  (const float*)d_in[13]};
    const float* beta[2]  = {(const float*)d_in[8],  (const float*)d_in[14]};

    // dtype detection + CSR build (shared by both layers)
    k_detect<<<1, 256>>>((const int*)ei);
    k_zero_cnt<<<(NN + 255) / 256, 256>>>();
    k_count<<<(EP + 255) / 256, 256>>>(ei);
    k_blocksum<<<NSCAN, 256>>>();
    k_scanblk<<<1, 32>>>();
    k_localscan<<<NSCAN, SCAN_BLK>>>();
    k_fill<<<(EP + 255) / 256, 256>>>(ei);

    bool both_outputs = (out_size >= 2 * NN * C);
    float* saved_ptr = both_outputs ? (out + (size_t)NN * C) : nullptr; // nullptr -> g_tmp

    // ---- layer 0: x -> (GAT) g_tmp -> (BN/ReLU) g_x1
    k_gemm<<<NN / 16, 256>>>(x, W[0]);
    k_al<<<NN, 256>>>(asrc[0], adst[0]);
    k_agg<<<(NN + 7) / 8, 256>>>(bias[0], nullptr);              // -> g_tmp
    k_bn_zero<<<1, 128>>>();
    k_bn_sum<<<250, 256>>>(nullptr);                              // from g_tmp
    k_bn_final<<<1, 64>>>(gamma[0], beta[0]);
    k_bn_apply<<<(NN * C + 255) / 256, 256>>>(nullptr, nullptr);  // g_tmp -> g_x1

    // ---- layer 1: g_x1 -> (GAT) saved -> (BN/ReLU) out
    k_gemm<<<NN / 16, 256>>>(nullptr, W[1]);                      // from g_x1
    k_al<<<NN, 256>>>(asrc[1], adst[1]);
    k_agg<<<(NN + 7) / 8, 256>>>(bias[1], saved_ptr);             // -> out[NN*C:] (saved)
    k_bn_zero<<<1, 128>>>();
    k_bn_sum<<<250, 256>>>(saved_ptr);                            // from saved
    k_bn_final<<<1, 64>>>(gamma[1], beta[1]);
    k_bn_apply<<<(NN * C + 255) / 256, 256>>>(saved_ptr, out);    // saved -> out[:NN*C]
}

// round 6
// speedup vs baseline: 2.3525x; 1.3439x over previous
#include <cuda_runtime.h>

#define NN 50000
#define NE 800000
#define EP (NE + NN)        // edges + self loops
#define C  64
#define H  4
#define HC 256              // H * C
#define NEG_SLOPE 0.2f
#define BN_EPS 1e-5f

#define SCAN_BLK 1024
#define NSCAN ((NN + SCAN_BLK - 1) / SCAN_BLK)   // 49

// ---------------- scratch (static device globals; no runtime alloc) ----------
__device__ float4 g_xh4[NN * (HC / 4)];   // xh: [NN][64] float4  (51.2 MB, fits L2)
__device__ float4 g_alsrc4[NN];           // per-node src logits, 4 heads
__device__ float4 g_aldst4[NN];           // per-node dst logits, 4 heads
__device__ float4 g_p4[EP];               // per-edge softmax numerators, 4 heads
__device__ float  g_x1[NN * C];           // layer-1 post BN/ReLU
__device__ float  g_tmp[NN * C];          // GAT output scratch
__device__ int    g_cnt[NN];
__device__ int    g_cur[NN];
__device__ int    g_off[NN + 1];
__device__ int    g_csr[EP];
__device__ int    g_bsum[NSCAN];
__device__ int    g_boff[NSCAN + 1];
__device__ float  g_bn[4 * C];            // [sum | sumsq | scale | shift]
__device__ int    g_is32;                 // 1 -> edge_index is int32, 0 -> int64
__device__ unsigned g_maxkey[4];          // encoded global max of alsrc per head

__device__ __forceinline__ float lrelu(float v) { return v > 0.f ? v : NEG_SLOPE * v; }

// order-preserving float <-> uint encoding for atomicMax
__device__ __forceinline__ unsigned fenc(float f) {
    unsigned u = __float_as_uint(f);
    return (u & 0x80000000u) ? ~u : (u | 0x80000000u);
}
__device__ __forceinline__ float fdec(unsigned k) {
    unsigned u = (k & 0x80000000u) ? (k & 0x7fffffffu) : ~k;
    return __uint_as_float(u);
}

// Safe edge-index read: dtype chosen at runtime, result clamped into [0, NN).
__device__ __forceinline__ int edge_val(const void* ei, int pos) {
    long long v = g_is32 ? (long long)((const int*)ei)[pos]
                         : ((const long long*)ei)[pos];
    int r = (int)v;
    if (r < 0) r = 0;
    if (r >= NN) r = NN - 1;
    return r;
}

// ---------------- dtype detection -------------------------------------------
__global__ void k_detect(const int* __restrict__ ei32) {
    __shared__ int s_any;
    if (threadIdx.x == 0) s_any = 0;
    __syncthreads();
    for (int k = threadIdx.x; k < 4096; k += 256) {
        if (ei32[2 * k + 1] != 0) s_any = 1;   // benign race
    }
    __syncthreads();
    if (threadIdx.x == 0) g_is32 = s_any;
}

// ---------------- CSR build --------------------------------------------------
__global__ void k_zero_cnt() {
    int i = blockIdx.x * blockDim.x + threadIdx.x;
    if (i < NN) { g_cnt[i] = 0; g_cur[i] = 0; }
}

__global__ void k_count(const void* __restrict__ ei) {
    int e = blockIdx.x * blockDim.x + threadIdx.x;
    if (e >= EP) return;
    int dst = (e < NE) ? edge_val(ei, NE + e) : (e - NE);
    atomicAdd(&g_cnt[dst], 1);
}

// ---- decoupled 3-phase scan of g_cnt -> g_off -------------------------------
__global__ void k_blocksum() {
    __shared__ int sd[256];
    int t = threadIdx.x;
    int base = blockIdx.x * SCAN_BLK;
    int s = 0;
#pragma unroll
    for (int j = 0; j < 4; j++) {
        int i = base + t + j * 256;
        s += (i < NN) ? g_cnt[i] : 0;
    }
    sd[t] = s;
    __syncthreads();
    for (int o = 128; o >= 1; o >>= 1) {
        if (t < o) sd[t] += sd[t + o];
        __syncthreads();
    }
    if (t == 0) g_bsum[blockIdx.x] = sd[0];
}

__global__ void k_scanblk() {
    if (threadIdx.x == 0) {
        int run = 0;
        for (int b = 0; b < NSCAN; b++) { g_boff[b] = run; run += g_bsum[b]; }
        g_boff[NSCAN] = run;
        g_off[NN] = run;
    }
}

__global__ void k_localscan() {
    __shared__ int swarp[32];
    int t = threadIdx.x, lane = t & 31, wid = t >> 5;
    int i = blockIdx.x * SCAN_BLK + t;
    int v = (i < NN) ? g_cnt[i] : 0;
    int incl = v;
#pragma unroll
    for (int o = 1; o < 32; o <<= 1) {
        int u = __shfl_up_sync(0xffffffffu, incl, o);
        if (lane >= o) incl += u;
    }
    if (lane == 31) swarp[wid] = incl;
    __syncthreads();
    if (wid == 0) {
        int s = swarp[lane];
        int in2 = s;
#pragma unroll
        for (int o = 1; o < 32; o <<= 1) {
            int u = __shfl_up_sync(0xffffffffu, in2, o);
            if (lane >= o) in2 += u;
        }
        swarp[lane] = in2 - s;
    }
    __syncthreads();
    if (i < NN) g_off[i] = (incl - v) + swarp[wid] + g_boff[blockIdx.x];
}

__global__ void k_fill(const void* __restrict__ ei) {
    int e = blockIdx.x * blockDim.x + threadIdx.x;
    if (e >= EP) return;
    int src, dst;
    if (e < NE) { src = edge_val(ei, e); dst = edge_val(ei, NE + e); }
    else        { src = e - NE;          dst = e - NE; }
    int idx = g_off[dst] + atomicAdd(&g_cur[dst], 1);
    if (idx >= 0 && idx < EP) g_csr[idx] = src;
}

// ---------------- GEMM: xh = xin @ W  (register-blocked 64x256, 8x8/thread) ---
// xin_ext == nullptr -> read from g_x1
__global__ void __launch_bounds__(256) k_gemm(const float* __restrict__ xin_ext,
                                              const float* __restrict__ W) {
    const float* xin = xin_ext ? xin_ext : g_x1;
    float* xh = (float*)g_xh4;
    __shared__ float4 at4[64 * 17];          // A^T tile: [k][row], 68-float rows (pad)
    float* at = (float*)at4;
    int t = threadIdx.x;
    int row0 = blockIdx.x * 64;

    // load A tile transposed: at[k*68 + row] = xin[(row0+row)*64 + k]
#pragma unroll
    for (int j = 0; j < 16; j++) {
        int idx = t + j * 256;               // 0..4095
        int row = idx >> 6, k = idx & 63;
        int gr = row0 + row;
        at[k * 68 + row] = (gr < NN) ? xin[(size_t)gr * 64 + k] : 0.f;
    }
    __syncthreads();

    int rbase = (t >> 5) * 8;                // 0,8,...,56  (warp-uniform)
    int cbase = (t & 31) * 8;                // 0,8,...,248
    const float4* Wv = (const float4*)W;

    float acc[8][8];
#pragma unroll
    for (int r = 0; r < 8; r++)
#pragma unroll
        for (int c = 0; c < 8; c++) acc[r][c] = 0.f;

    for (int k = 0; k < 64; k++) {
        float4 a0 = at4[k * 17 + (rbase >> 2)];
        float4 a1 = at4[k * 17 + (rbase >> 2) + 1];
        float4 w0 = __ldg(&Wv[(k * HC + cbase) >> 2]);
        float4 w1 = __ldg(&Wv[((k * HC + cbase) >> 2) + 1]);
        float a[8] = {a0.x, a0.y, a0.z, a0.w, a1.x, a1.y, a1.z, a1.w};
        float w[8] = {w0.x, w0.y, w0.z, w0.w, w1.x, w1.y, w1.z, w1.w};
#pragma unroll
        for (int r = 0; r < 8; r++)
#pragma unroll
            for (int c = 0; c < 8; c++) acc[r][c] = fmaf(a[r], w[c], acc[r][c]);
    }

#pragma unroll
    for (int r = 0; r < 8; r++) {
        int row = row0 + rbase + r;
        if (row < NN) {
            float4* dst = &g_xh4[((size_t)row * HC + cbase) >> 2];
            dst[0] = make_float4(acc[r][0], acc[r][1], acc[r][2], acc[r][3]);
            dst[1] = make_float4(acc[r][4], acc[r][5], acc[r][6], acc[r][7]);
        }
    }
}

// ---------------- init global max keys ---------------------------------------
__global__ void k_initmax() {
    if (threadIdx.x < 4) g_maxkey[threadIdx.x] = 0u;
}

// ---------------- attention logits (warp per node) + global max --------------
__global__ void k_al(const float* __restrict__ asrc, const float* __restrict__ adst) {
    __shared__ float sa[256], sdd[256];
    __shared__ unsigned bm[4];
    int t = threadIdx.x;
    sa[t] = asrc[t]; sdd[t] = adst[t];
    if (t < 4) bm[t] = 0u;
    __syncthreads();
    int warp = t >> 5, lane = t & 31;
    int n = blockIdx.x * 8 + warp;           // 6250*8 == NN exactly
    const float4* xr = &g_xh4[(size_t)n * (HC / 4)];
    float4 v0 = xr[lane];                    // cols 4l..4l+3   (head lane>>4)
    float4 v1 = xr[32 + lane];               // cols 128+4l..   (head 2+(lane>>4))
    int c0 = 4 * lane, c1 = 128 + 4 * lane;
    float s0 = v0.x*sa[c0] + v0.y*sa[c0+1] + v0.z*sa[c0+2] + v0.w*sa[c0+3];
    float s1 = v1.x*sa[c1] + v1.y*sa[c1+1] + v1.z*sa[c1+2] + v1.w*sa[c1+3];
    float d0 = v0.x*sdd[c0] + v0.y*sdd[c0+1] + v0.z*sdd[c0+2] + v0.w*sdd[c0+3];
    float d1 = v1.x*sdd[c1] + v1.y*sdd[c1+1] + v1.z*sdd[c1+2] + v1.w*sdd[c1+3];
#pragma unroll
    for (int o = 8; o >= 1; o >>= 1) {       // reduce within 16-lane halves
        s0 += __shfl_xor_sync(0xffffffffu, s0, o);
        s1 += __shfl_xor_sync(0xffffffffu, s1, o);
        d0 += __shfl_xor_sync(0xffffffffu, d0, o);
        d1 += __shfl_xor_sync(0xffffffffu, d1, o);
    }
    if (lane == 0 || lane == 16) {
        int h = lane >> 4;                   // 0 or 1
        ((float*)&g_alsrc4[n])[h]     = s0;
        ((float*)&g_alsrc4[n])[2 + h] = s1;
        ((float*)&g_aldst4[n])[h]     = d0;
        ((float*)&g_aldst4[n])[2 + h] = d1;
        atomicMax(&bm[h],     fenc(s0));
        atomicMax(&bm[2 + h], fenc(s1));
    }
    __syncthreads();
    if (t < 4) atomicMax(&g_maxkey[t], bm[t]);
}

// ---------------- fused softmax + aggregate (one warp per node) --------------
// m_h = max(global_max(alsrc_h) + aldst_h, 0) >= lrelu(as+ad): softmax is
// shift-invariant; logit spread << 87 so no underflow of the denominator.
__global__ void k_agg(const float* __restrict__ bias, float* __restrict__ out_ext) {
    float* out = out_ext ? out_ext : g_tmp;
    __shared__ float4 sm4[8][64];
    int warp = threadIdx.x >> 5, lane = threadIdx.x & 31;
    int n = blockIdx.x * 8 + warp;
    if (n >= NN) return;
    int beg = g_off[n], end = g_off[n + 1];
    float4 ad = g_aldst4[n];
    float m0 = fmaxf(fdec(g_maxkey[0]) + ad.x, 0.f);
    float m1 = fmaxf(fdec(g_maxkey[1]) + ad.y, 0.f);
    float m2 = fmaxf(fdec(g_maxkey[2]) + ad.z, 0.f);
    float m3 = fmaxf(fdec(g_maxkey[3]) + ad.w, 0.f);

    // pass B: p = exp(e - m), denom  (single gather pass)
    float d0 = 0.f, d1 = 0.f, d2 = 0.f, d3 = 0.f;
    for (int i = beg + lane; i < end; i += 32) {
        int s = g_csr[i];
        float4 as = g_alsrc4[s];
        float p0 = __expf(lrelu(as.x + ad.x) - m0);
        float p1 = __expf(lrelu(as.y + ad.y) - m1);
        float p2 = __expf(lrelu(as.z + ad.z) - m2);
        float p3 = __expf(lrelu(as.w + ad.w) - m3);
        d0 += p0; d1 += p1; d2 += p2; d3 += p3;
        g_p4[i] = make_float4(p0, p1, p2, p3);
    }
#pragma unroll
    for (int o = 16; o; o >>= 1) {
        d0 += __shfl_xor_sync(0xffffffffu, d0, o);
        d1 += __shfl_xor_sync(0xffffffffu, d1, o);
        d2 += __shfl_xor_sync(0xffffffffu, d2, o);
        d3 += __shfl_xor_sync(0xffffffffu, d3, o);
    }
    float iv0 = 1.f / (d0 + 1e-16f), iv1 = 1.f / (d1 + 1e-16f);
    float iv2 = 1.f / (d2 + 1e-16f), iv3 = 1.f / (d3 + 1e-16f);

    // pass C: gather xh[src], alpha-weighted accumulate (whole warp per edge)
    int hsel = lane >> 4;
    float iva = hsel ? iv1 : iv0;
    float ivb = hsel ? iv3 : iv2;
    float4 acc0 = make_float4(0.f, 0.f, 0.f, 0.f);
    float4 acc1 = make_float4(0.f, 0.f, 0.f, 0.f);
    for (int i = beg; i < end; i++) {
        int s = g_csr[i];
        float4 p4 = g_p4[i];
        float a0 = (hsel ? p4.y : p4.x) * iva;
        float a1 = (hsel ? p4.w : p4.z) * ivb;
        const float4* xr = &g_xh4[(size_t)s * (HC / 4)];
        float4 v0 = xr[lane];
        float4 v1 = xr[32 + lane];
        acc0.x = fmaf(a0, v0.x, acc0.x); acc0.y = fmaf(a0, v0.y, acc0.y);
        acc0.z = fmaf(a0, v0.z, acc0.z); acc0.w = fmaf(a0, v0.w, acc0.w);
        acc1.x = fmaf(a1, v1.x, acc1.x); acc1.y = fmaf(a1, v1.y, acc1.y);
        acc1.z = fmaf(a1, v1.z, acc1.z); acc1.w = fmaf(a1, v1.w, acc1.w);
    }
    sm4[warp][lane]      = acc0;
    sm4[warp][32 + lane] = acc1;
    __syncwarp();
    const float* smf = (const float*)sm4[warp];
#pragma unroll
    for (int j = 0; j < 2; j++) {
        int c = lane + 32 * j;
        float v = (smf[c] + smf[c + 64] + smf[c + 128] + smf[c + 192]) * 0.25f
                  + __ldg(&bias[c]);
        out[(size_t)n * C + c] = v;
    }
}

// ---------------- BatchNorm --------------------------------------------------
__global__ void k_bn_zero() {
    int t = threadIdx.x;
    if (t < 128) g_bn[t] = 0.f;
}

__global__ void k_bn_sum(const float* __restrict__ xin_ext) {
    const float* x = xin_ext ? xin_ext : g_tmp;
    __shared__ float s1[256], s2[256];
    int t = threadIdx.x;
    int c = t & 63, q = t >> 6;
    int r0 = blockIdx.x * 200;
    float s = 0.f, ss = 0.f;
    for (int r = r0 + q; r < r0 + 200; r += 4) {
        float v = x[(size_t)r * 64 + c];
        s += v; ss += v * v;
    }
    s1[t] = s; s2[t] = ss;
    __syncthreads();
    if (t < 128) { s1[t] += s1[t + 128]; s2[t] += s2[t + 128]; }
    __syncthreads();
    if (t < 64) {
        atomicAdd(&g_bn[c],      s1[t] + s1[t + 64]);
        atomicAdd(&g_bn[64 + c], s2[t] + s2[t + 64]);
    }
}

__global__ void k_bn_final(const float* __restrict__ gamma, const float* __restrict__ beta) {
    int c = threadIdx.x;
    if (c >= 64) return;
    float mean = g_bn[c] * (1.f / NN);
    float var  = g_bn[64 + c] * (1.f / NN) - mean * mean;
    float sc = __ldg(&gamma[c]) * rsqrtf(var + BN_EPS);
    g_bn[128 + c] = sc;
    g_bn[192 + c] = __ldg(&beta[c]) - mean * sc;
}

__global__ void k_bn_apply(const float* __restrict__ in_ext, float* __restrict__ out_ext) {
    const float* in = in_ext ? in_ext : g_tmp;
    float* out = out_ext ? out_ext : g_x1;
    int i = blockIdx.x * blockDim.x + threadIdx.x;
    if (i >= NN * C) return;
    int c = i & 63;
    float v = g_bn[128 + c] * in[i] + g_bn[192 + c];
    out[i] = fmaxf(v, 0.f);
}

// ---------------- launch -----------------------------------------------------
extern "C" void kernel_launch(void* const* d_in, const int* in_sizes, int n_in,
                              void* d_out, int out_size) {
    const float* x  = (const float*)d_in[0];
    const void*  ei = d_in[1];                 // int32 or int64, detected on device
    float* out = (float*)d_out;

    const float* W[2]     = {(const float*)d_in[3],  (const float*)d_in[9]};
    const float* asrc[2]  = {(const float*)d_in[4],  (const float*)d_in[10]};
    const float* adst[2]  = {(const float*)d_in[5],  (const float*)d_in[11]};
    const float* bias[2]  = {(const float*)d_in[6],  (const float*)d_in[12]};
    const float* gamma[2] = {(const float*)d_in[7],  (const float*)d_in[13]};
    const float* beta[2]  = {(const float*)d_in[8],  (const float*)d_in[14]};

    // dtype detection + CSR build (shared by both layers)
    k_detect<<<1, 256>>>((const int*)ei);
    k_zero_cnt<<<(NN + 255) / 256, 256>>>();
    k_count<<<(EP + 255) / 256, 256>>>(ei);
    k_blocksum<<<NSCAN, 256>>>();
    k_scanblk<<<1, 32>>>();
    k_localscan<<<NSCAN, SCAN_BLK>>>();
    k_fill<<<(EP + 255) / 256, 256>>>(ei);

    bool both_outputs = (out_size >= 2 * NN * C);
    float* saved_ptr = both_outputs ? (out + (size_t)NN * C) : nullptr; // nullptr -> g_tmp

    // ---- layer 0: x -> (GAT) g_tmp -> (BN/ReLU) g_x1
    k_gemm<<<(NN + 63) / 64, 256>>>(x, W[0]);
    k_initmax<<<1, 32>>>();
    k_al<<<NN / 8, 256>>>(asrc[0], adst[0]);
    k_agg<<<(NN + 7) / 8, 256>>>(bias[0], nullptr);
    k_bn_zero<<<1, 128>>>();
    k_bn_sum<<<250, 256>>>(nullptr);
    k_bn_final<<<1, 64>>>(gamma[0], beta[0]);
    k_bn_apply<<<(NN * C + 255) / 256, 256>>>(nullptr, nullptr);

    // ---- layer 1: g_x1 -> (GAT) saved -> (BN/ReLU) out
    k_gemm<<<(NN + 63) / 64, 256>>>(nullptr, W[1]);
    k_initmax<<<1, 32>>>();
    k_al<<<NN / 8, 256>>>(asrc[1], adst[1]);
    k_agg<<<(NN + 7) / 8, 256>>>(bias[1], saved_ptr);
    k_bn_zero<<<1, 128>>>();
    k_bn_sum<<<250, 256>>>(saved_ptr);
    k_bn_final<<<1, 64>>>(gamma[1], beta[1]);
    k_bn_apply<<<(NN * C + 255) / 256, 256>>>(saved_ptr, out);
}